// round 1
// baseline (speedup 1.0000x reference)
#include <cuda_runtime.h>
#include <math.h>
#include <stdint.h>

#define NN 50000
#define RR 3
#define EE 600000
#define DD 128
#define LL 3

// ---------------- scratch (device globals; no allocations allowed) ----------------
__device__ float g_z[(size_t)RR * NN * DD];      // projected features per etype
__device__ float g_el[RR * NN];
__device__ float g_er[RR * NN];
__device__ float g_m[RR * NN];                   // segment max
__device__ float g_ssum[RR * NN];                // segment sum of exp
__device__ int   g_cnt[RR * NN];                 // histogram / cursor
__device__ int   g_off[RR * (NN + 1)];           // CSR offsets
__device__ int   g_csr_src[RR * EE];
__device__ float g_csr_ex[RR * EE];
__device__ float g_ebuf[RR * EE];                // leaky(e) per original edge
__device__ float g_b0[(size_t)NN * DD];          // ping-pong h buffers
__device__ float g_b1[(size_t)NN * DD];
__device__ float g_sum[DD];
__device__ float g_sumsq[DD];
__device__ float g_scale[DD];
__device__ float g_shift[DD];

// ---------------- init per layer ----------------
__global__ void init_kernel() {
    int i = blockIdx.x * blockDim.x + threadIdx.x;
    if (i < RR * NN) {
        g_m[i]    = __int_as_float(0xFF800000);  // -inf
        g_ssum[i] = 0.f;
        g_cnt[i]  = 0;
    }
    if (i < DD) { g_sum[i] = 0.f; g_sumsq[i] = 0.f; }
}

// ---------------- fused GEMM z = h @ W  + el/er epilogue ----------------
// tile 128x128, BK=8, 256 threads, 8x8 per-thread micro-tile
#define BM 128
#define BN 128
#define BK 8
#define TM 8
#define TN 8

__global__ __launch_bounds__(256) void gemm_attn_kernel(
    const float* __restrict__ h,        // [NN, DD]
    const float* __restrict__ Wlayer,   // [RR, DD, DD]
    const float* __restrict__ al_layer, // [RR, DD]
    const float* __restrict__ ar_layer) // [RR, DD]
{
    int r = blockIdx.y;
    const float* W = Wlayer + (size_t)r * DD * DD;
    int rowBase = blockIdx.x * BM;

    __shared__ float As[BK][BM];   // transposed A tile
    __shared__ float Bs[BK][BN];

    int tid  = threadIdx.x;
    int tcol = tid & 15;    // 0..15 -> cols tcol*8
    int trow = tid >> 4;    // 0..15 -> rows trow*8

    float acc[TM][TN];
#pragma unroll
    for (int i = 0; i < TM; i++)
#pragma unroll
        for (int j = 0; j < TN; j++) acc[i][j] = 0.f;

    int a_row = tid >> 1;          // 0..127
    int a_k4  = (tid & 1) * 4;     // 0 or 4
    int b_k   = tid >> 5;          // 0..7
    int b_c   = (tid & 31) * 4;    // 0..124

    for (int k0 = 0; k0 < DD; k0 += BK) {
        float4 av = make_float4(0.f, 0.f, 0.f, 0.f);
        int grow = rowBase + a_row;
        if (grow < NN) av = *(const float4*)(h + (size_t)grow * DD + k0 + a_k4);
        As[a_k4 + 0][a_row] = av.x;
        As[a_k4 + 1][a_row] = av.y;
        As[a_k4 + 2][a_row] = av.z;
        As[a_k4 + 3][a_row] = av.w;
        *(float4*)(&Bs[b_k][b_c]) = *(const float4*)(W + (size_t)(k0 + b_k) * DD + b_c);
        __syncthreads();
#pragma unroll
        for (int k = 0; k < BK; ++k) {
            float4 a0 = *(const float4*)(&As[k][trow * TM]);
            float4 a1 = *(const float4*)(&As[k][trow * TM + 4]);
            float4 b0 = *(const float4*)(&Bs[k][tcol * TN]);
            float4 b1 = *(const float4*)(&Bs[k][tcol * TN + 4]);
            float ar_[TM] = {a0.x, a0.y, a0.z, a0.w, a1.x, a1.y, a1.z, a1.w};
            float br_[TN] = {b0.x, b0.y, b0.z, b0.w, b1.x, b1.y, b1.z, b1.w};
#pragma unroll
            for (int i = 0; i < TM; i++)
#pragma unroll
                for (int j = 0; j < TN; j++) acc[i][j] += ar_[i] * br_[j];
        }
        __syncthreads();
    }

    // write z
    float* zr = g_z + (size_t)r * NN * DD;
#pragma unroll
    for (int i = 0; i < TM; i++) {
        int grow = rowBase + trow * TM + i;
        if (grow < NN) {
            float4 v0 = make_float4(acc[i][0], acc[i][1], acc[i][2], acc[i][3]);
            float4 v1 = make_float4(acc[i][4], acc[i][5], acc[i][6], acc[i][7]);
            *(float4*)(zr + (size_t)grow * DD + tcol * TN)     = v0;
            *(float4*)(zr + (size_t)grow * DD + tcol * TN + 4) = v1;
        }
    }

    // el/er epilogue: per-row dot with attn vectors, reduce over 16-lane groups
    const float* al = al_layer + (size_t)r * DD;
    const float* ar = ar_layer + (size_t)r * DD;
    float alv[TN], arv[TN];
#pragma unroll
    for (int j = 0; j < TN; j++) {
        alv[j] = al[tcol * TN + j];
        arv[j] = ar[tcol * TN + j];
    }
#pragma unroll
    for (int i = 0; i < TM; i++) {
        float pl = 0.f, pr = 0.f;
#pragma unroll
        for (int j = 0; j < TN; j++) {
            pl += acc[i][j] * alv[j];
            pr += acc[i][j] * arv[j];
        }
#pragma unroll
        for (int o = 8; o >= 1; o >>= 1) {
            pl += __shfl_xor_sync(0xFFFFFFFFu, pl, o);
            pr += __shfl_xor_sync(0xFFFFFFFFu, pr, o);
        }
        int grow = rowBase + trow * TM + i;
        if ((tid & 15) == 0 && grow < NN) {
            g_el[r * NN + grow] = pl;
            g_er[r * NN + grow] = pr;
        }
    }
}

// ---------------- edge pass 1: leaky, histogram, segment max ----------------
__global__ void edge1_kernel(const int* __restrict__ src, const int* __restrict__ dst) {
    int r = blockIdx.y;
    int e = blockIdx.x * blockDim.x + threadIdx.x;
    if (e >= EE) return;
    int s = src[(size_t)r * EE + e];
    int d = dst[(size_t)r * EE + e];
    float v = g_el[r * NN + s] + g_er[r * NN + d];
    v = v > 0.f ? v : 0.2f * v;
    g_ebuf[(size_t)r * EE + e] = v;
    atomicAdd(&g_cnt[r * NN + d], 1);
    // float atomic max via signed-max / unsigned-min trick
    if (v >= 0.f) atomicMax((int*)&g_m[r * NN + d], __float_as_int(v));
    else          atomicMin((unsigned int*)&g_m[r * NN + d], __float_as_uint(v));
}

// ---------------- exclusive scan of counts -> offsets (one block per etype) --------
__global__ void scan_kernel() {
    int r = blockIdx.x;
    __shared__ int s[1024];
    int carry = 0;
    for (int base = 0; base < NN; base += 1024) {
        int i = base + threadIdx.x;
        int v = (i < NN) ? g_cnt[r * NN + i] : 0;
        s[threadIdx.x] = v;
        __syncthreads();
        for (int o = 1; o < 1024; o <<= 1) {
            int t = (threadIdx.x >= o) ? s[threadIdx.x - o] : 0;
            __syncthreads();
            s[threadIdx.x] += t;
            __syncthreads();
        }
        if (i < NN) {
            g_off[r * (NN + 1) + i] = carry + s[threadIdx.x] - v;
            g_cnt[r * NN + i] = 0;   // reset for use as cursor
        }
        carry += s[1023];
        __syncthreads();
    }
    if (threadIdx.x == 0) g_off[r * (NN + 1) + NN] = carry;
}

// ---------------- edge pass 2: fill CSR, exp, segment sum ----------------
__global__ void fill_kernel(const int* __restrict__ src, const int* __restrict__ dst) {
    int r = blockIdx.y;
    int e = blockIdx.x * blockDim.x + threadIdx.x;
    if (e >= EE) return;
    int d = dst[(size_t)r * EE + e];
    int pos = g_off[r * (NN + 1) + d] + atomicAdd(&g_cnt[r * NN + d], 1);
    g_csr_src[(size_t)r * EE + pos] = src[(size_t)r * EE + e];
    float ex = __expf(g_ebuf[(size_t)r * EE + e] - g_m[r * NN + d]);
    g_csr_ex[(size_t)r * EE + pos] = ex;
    atomicAdd(&g_ssum[r * NN + d], ex);
}

// ---------------- heavy pass: per-dst aggregation, fused residual+bias+relu+sum ----
__global__ __launch_bounds__(256) void heavy_kernel(
    int r,
    const float* __restrict__ hin,
    const float* __restrict__ bias_r, // [DD]
    float* __restrict__ t,
    int accum, int dorelu)
{
    int warp = (blockIdx.x * blockDim.x + threadIdx.x) >> 5;
    int lane = threadIdx.x & 31;
    if (warp >= NN) return;
    int n = warp;
    int b0 = g_off[r * (NN + 1) + n];
    int b1 = g_off[r * (NN + 1) + n + 1];
    float inv = (b1 > b0) ? (1.f / g_ssum[r * NN + n]) : 0.f;

    const float* zr = g_z + (size_t)r * NN * DD;
    const int*   cs = g_csr_src + (size_t)r * EE;
    const float* cx = g_csr_ex + (size_t)r * EE;

    float4 acc = make_float4(0.f, 0.f, 0.f, 0.f);
    for (int idx = b0; idx < b1; ++idx) {
        int   s = cs[idx];
        float a = cx[idx] * inv;
        float4 zv = *(const float4*)(zr + (size_t)s * DD + lane * 4);
        acc.x += a * zv.x; acc.y += a * zv.y;
        acc.z += a * zv.z; acc.w += a * zv.w;
    }
    float4 hv = *(const float4*)(hin + (size_t)n * DD + lane * 4);
    float4 bv = *(const float4*)(bias_r + lane * 4);
    float4 v = make_float4(acc.x + hv.x + bv.x, acc.y + hv.y + bv.y,
                           acc.z + hv.z + bv.z, acc.w + hv.w + bv.w);
    if (dorelu) {
        v.x = fmaxf(v.x, 0.f); v.y = fmaxf(v.y, 0.f);
        v.z = fmaxf(v.z, 0.f); v.w = fmaxf(v.w, 0.f);
    }
    float4* tp = (float4*)(t + (size_t)n * DD + lane * 4);
    if (accum) {
        float4 old = *tp;
        v.x += old.x; v.y += old.y; v.z += old.z; v.w += old.w;
    }
    *tp = v;
}

// ---------------- BatchNorm: column stats ----------------
__global__ void bnstat_kernel(const float* __restrict__ t) {
    int col  = threadIdx.x & 127;
    int half = threadIdx.x >> 7;
    float s = 0.f, s2 = 0.f;
    for (int n = blockIdx.x * 2 + half; n < NN; n += gridDim.x * 2) {
        float v = t[(size_t)n * DD + col];
        s += v; s2 += v * v;
    }
    __shared__ float sh[256], sh2[256];
    sh[threadIdx.x] = s; sh2[threadIdx.x] = s2;
    __syncthreads();
    if (half == 0) {
        s  += sh[threadIdx.x + 128];
        s2 += sh2[threadIdx.x + 128];
        atomicAdd(&g_sum[col], s);
        atomicAdd(&g_sumsq[col], s2);
    }
}

__global__ void bnfin_kernel(const float* __restrict__ gamma, const float* __restrict__ beta) {
    int c = threadIdx.x;
    float invN = 1.f / (float)NN;
    float mu  = g_sum[c] * invN;
    float var = g_sumsq[c] * invN - mu * mu;
    float rs  = rsqrtf(var + 1e-5f);
    float g   = gamma[c];
    g_scale[c] = rs * g;
    g_shift[c] = beta[c] - mu * rs * g;
}

__global__ void bnnorm_kernel(const float* __restrict__ t, float* __restrict__ outp) {
    size_t i = (size_t)blockIdx.x * blockDim.x + threadIdx.x;  // float4 index
    if (i >= (size_t)NN * DD / 4) return;
    int c4 = (int)(i & 31) * 4;
    float4 v = ((const float4*)t)[i];
    v.x = v.x * g_scale[c4 + 0] + g_shift[c4 + 0];
    v.y = v.y * g_scale[c4 + 1] + g_shift[c4 + 1];
    v.z = v.z * g_scale[c4 + 2] + g_shift[c4 + 2];
    v.w = v.w * g_scale[c4 + 3] + g_shift[c4 + 3];
    ((float4*)outp)[i] = v;
}

// ---------------- launcher ----------------
extern "C" void kernel_launch(void* const* d_in, const int* in_sizes, int n_in,
                              void* d_out, int out_size) {
    const float* x     = (const float*)d_in[0];
    const int*   src   = (const int*)d_in[1];
    const int*   dst   = (const int*)d_in[2];
    const float* Ws    = (const float*)d_in[3];
    const float* attnl = (const float*)d_in[4];
    const float* attnr = (const float*)d_in[5];
    const float* bias  = (const float*)d_in[6];
    const float* gamma = (const float*)d_in[7];
    const float* beta  = (const float*)d_in[8];
    float* out = (float*)d_out;

    float *p_b0 = nullptr, *p_b1 = nullptr;
    cudaGetSymbolAddress((void**)&p_b0, g_b0);
    cudaGetSymbolAddress((void**)&p_b1, g_b1);

    dim3 gemm_grid((NN + BM - 1) / BM, RR);
    dim3 edge_grid((EE + 255) / 256, RR);
    int init_blocks  = (RR * NN + 255) / 256;
    int heavy_blocks = (NN * 32 + 255) / 256;
    int norm_blocks  = ((NN * DD / 4) + 255) / 256;

    for (int i = 0; i < LL; i++) {
        const float* hin = (i == 0) ? x : (i == 1 ? p_b0 : p_b1);
        float* tbuf      = (i == 0) ? p_b0 : (i == 1 ? p_b1 : out);

        init_kernel<<<init_blocks, 256>>>();
        gemm_attn_kernel<<<gemm_grid, 256>>>(hin,
                                             Ws    + (size_t)i * RR * DD * DD,
                                             attnl + (size_t)i * RR * DD,
                                             attnr + (size_t)i * RR * DD);
        edge1_kernel<<<edge_grid, 256>>>(src, dst);
        scan_kernel<<<RR, 1024>>>();
        fill_kernel<<<edge_grid, 256>>>(src, dst);
        for (int r = 0; r < RR; r++) {
            heavy_kernel<<<heavy_blocks, 256>>>(r, hin,
                                                bias + ((size_t)i * RR + r) * DD,
                                                tbuf, /*accum=*/(r > 0), /*dorelu=*/(i < LL - 1));
        }
        bnstat_kernel<<<296, 256>>>(tbuf);
        bnfin_kernel<<<1, DD>>>(gamma + (size_t)i * DD, beta + (size_t)i * DD);
        bnnorm_kernel<<<norm_blocks, 256>>>(tbuf, tbuf);
    }
}

// round 2
// speedup vs baseline: 1.2826x; 1.2826x over previous
#include <cuda_runtime.h>
#include <math.h>
#include <stdint.h>

#define NN 50000
#define RR 3
#define EE 600000
#define DD 128
#define LL 3
#define SCAN_B 49   // ceil(50000/1024)

// ---------------- scratch (device globals) ----------------
__device__ float g_z[(size_t)RR * NN * DD];      // projected features per etype
__device__ float g_el[RR * NN];
__device__ float g_er[RR * NN];
__device__ int   g_cnt[RR * NN];                 // histogram / cursor
__device__ int   g_off[RR * (NN + 1)];           // CSR offsets
__device__ int   g_part[RR * 64];                // scan partials
__device__ int   g_csr_src[RR * EE];
__device__ float g_b0[(size_t)NN * DD];          // ping-pong h buffers
__device__ float g_b1[(size_t)NN * DD];
__device__ float g_sum[DD];
__device__ float g_sumsq[DD];
__device__ float g_scale[DD];
__device__ float g_shift[DD];

// ---------------- CSR build (once per launch) ----------------
__global__ void count_kernel(const int* __restrict__ dst) {
    int r = blockIdx.y;
    int e = blockIdx.x * blockDim.x + threadIdx.x;
    if (e < EE) atomicAdd(&g_cnt[r * NN + dst[(size_t)r * EE + e]], 1);
}

__global__ void scan1_kernel() {
    int r = blockIdx.y;
    int b = blockIdx.x;
    int i = b * 1024 + threadIdx.x;
    __shared__ int s[1024];
    int v = (i < NN) ? g_cnt[r * NN + i] : 0;
    s[threadIdx.x] = v;
    __syncthreads();
    for (int o = 1; o < 1024; o <<= 1) {
        int t = (threadIdx.x >= o) ? s[threadIdx.x - o] : 0;
        __syncthreads();
        s[threadIdx.x] += t;
        __syncthreads();
    }
    if (i < NN) {
        g_off[r * (NN + 1) + i] = s[threadIdx.x] - v;  // exclusive, no carry yet
        g_cnt[r * NN + i] = 0;                         // reset -> fill cursor
    }
    if (threadIdx.x == 1023) g_part[r * 64 + b] = s[1023];
}

__global__ void scan2_kernel() {
    int r = threadIdx.x;
    if (r >= RR) return;
    int run = 0;
    for (int b = 0; b < SCAN_B; b++) {
        int t = g_part[r * 64 + b];
        g_part[r * 64 + b] = run;
        run += t;
    }
    g_off[r * (NN + 1) + NN] = run;
}

__global__ void scan3_kernel() {
    int r = blockIdx.y;
    int b = blockIdx.x;
    int i = b * 1024 + threadIdx.x;
    if (i < NN) g_off[r * (NN + 1) + i] += g_part[r * 64 + b];
}

__global__ void fill_kernel(const int* __restrict__ src, const int* __restrict__ dst) {
    int r = blockIdx.y;
    int e = blockIdx.x * blockDim.x + threadIdx.x;
    if (e >= EE) return;
    int d = dst[(size_t)r * EE + e];
    int pos = g_off[r * (NN + 1) + d] + atomicAdd(&g_cnt[r * NN + d], 1);
    g_csr_src[(size_t)r * EE + pos] = src[(size_t)r * EE + e];
}

// ---------------- fused GEMM z = h @ W  + el/er epilogue (FFMA2) ----------------
#define BM 128
#define BN 128
#define BK 8
#define TM 8
#define TN 8

__global__ __launch_bounds__(256) void gemm_attn_kernel(
    const float* __restrict__ h,        // [NN, DD]
    const float* __restrict__ Wlayer,   // [RR, DD, DD]
    const float* __restrict__ al_layer, // [RR, DD]
    const float* __restrict__ ar_layer) // [RR, DD]
{
    int r = blockIdx.y;
    const float* W = Wlayer + (size_t)r * DD * DD;
    int rowBase = blockIdx.x * BM;

    __shared__ float As[BK][BM];   // transposed A tile
    __shared__ float Bs[BK][BN];

    int tid  = threadIdx.x;
    int tcol = tid & 15;    // cols tcol*8
    int trow = tid >> 4;    // rows trow*8

    unsigned long long acc2[TM][TN / 2];
#pragma unroll
    for (int i = 0; i < TM; i++)
#pragma unroll
        for (int j = 0; j < TN / 2; j++) acc2[i][j] = 0ULL;

    int a_row = tid >> 1;
    int a_k4  = (tid & 1) * 4;
    int b_k   = tid >> 5;
    int b_c   = (tid & 31) * 4;

    for (int k0 = 0; k0 < DD; k0 += BK) {
        float4 av = make_float4(0.f, 0.f, 0.f, 0.f);
        int grow = rowBase + a_row;
        if (grow < NN) av = *(const float4*)(h + (size_t)grow * DD + k0 + a_k4);
        As[a_k4 + 0][a_row] = av.x;
        As[a_k4 + 1][a_row] = av.y;
        As[a_k4 + 2][a_row] = av.z;
        As[a_k4 + 3][a_row] = av.w;
        *(float4*)(&Bs[b_k][b_c]) = *(const float4*)(W + (size_t)(k0 + b_k) * DD + b_c);
        __syncthreads();
#pragma unroll
        for (int k = 0; k < BK; ++k) {
            float4 a0 = *(const float4*)(&As[k][trow * TM]);
            float4 a1 = *(const float4*)(&As[k][trow * TM + 4]);
            float ar_[TM] = {a0.x, a0.y, a0.z, a0.w, a1.x, a1.y, a1.z, a1.w};
            const unsigned long long* bp =
                (const unsigned long long*)(&Bs[k][tcol * TN]);
            unsigned long long b2_[TN / 2];
#pragma unroll
            for (int j = 0; j < TN / 2; j++) b2_[j] = bp[j];
#pragma unroll
            for (int i = 0; i < TM; i++) {
                unsigned long long ad;
                asm("mov.b64 %0, {%1, %1};" : "=l"(ad) : "f"(ar_[i]));
#pragma unroll
                for (int j = 0; j < TN / 2; j++) {
                    asm("fma.rn.f32x2 %0, %1, %2, %0;"
                        : "+l"(acc2[i][j]) : "l"(ad), "l"(b2_[j]));
                }
            }
        }
        __syncthreads();
    }

    // unpack accumulators
    float acc[TM][TN];
#pragma unroll
    for (int i = 0; i < TM; i++)
#pragma unroll
        for (int j = 0; j < TN / 2; j++) {
            float lo, hi;
            asm("mov.b64 {%0, %1}, %2;" : "=f"(lo), "=f"(hi) : "l"(acc2[i][j]));
            acc[i][2 * j] = lo;
            acc[i][2 * j + 1] = hi;
        }

    // write z
    float* zr = g_z + (size_t)r * NN * DD;
#pragma unroll
    for (int i = 0; i < TM; i++) {
        int grow = rowBase + trow * TM + i;
        if (grow < NN) {
            float4 v0 = make_float4(acc[i][0], acc[i][1], acc[i][2], acc[i][3]);
            float4 v1 = make_float4(acc[i][4], acc[i][5], acc[i][6], acc[i][7]);
            *(float4*)(zr + (size_t)grow * DD + tcol * TN)     = v0;
            *(float4*)(zr + (size_t)grow * DD + tcol * TN + 4) = v1;
        }
    }

    // el/er epilogue
    const float* al = al_layer + (size_t)r * DD;
    const float* ar = ar_layer + (size_t)r * DD;
    float alv[TN], arv[TN];
#pragma unroll
    for (int j = 0; j < TN; j++) {
        alv[j] = al[tcol * TN + j];
        arv[j] = ar[tcol * TN + j];
    }
#pragma unroll
    for (int i = 0; i < TM; i++) {
        float pl = 0.f, pr = 0.f;
#pragma unroll
        for (int j = 0; j < TN; j++) {
            pl += acc[i][j] * alv[j];
            pr += acc[i][j] * arv[j];
        }
#pragma unroll
        for (int o = 8; o >= 1; o >>= 1) {
            pl += __shfl_xor_sync(0xFFFFFFFFu, pl, o);
            pr += __shfl_xor_sync(0xFFFFFFFFu, pr, o);
        }
        int grow = rowBase + trow * TM + i;
        if ((tid & 15) == 0 && grow < NN) {
            g_el[r * NN + grow] = pl;
            g_er[r * NN + grow] = pr;
        }
    }
}

// ---------------- fused softmax + aggregation over all etypes ----------------
__global__ __launch_bounds__(256) void heavy_all_kernel(
    const float* __restrict__ hin,
    const float* __restrict__ bias_layer, // [RR, DD]
    float* __restrict__ t,
    int dorelu)
{
    int warp = (blockIdx.x * blockDim.x + threadIdx.x) >> 5;
    int lane = threadIdx.x & 31;
    if (warp >= NN) return;
    int n = warp;

    float4 hv = *(const float4*)(hin + (size_t)n * DD + lane * 4);
    float4 tot = make_float4(0.f, 0.f, 0.f, 0.f);

#pragma unroll
    for (int r = 0; r < RR; r++) {
        int b0 = g_off[r * (NN + 1) + n];
        int b1 = g_off[r * (NN + 1) + n + 1];
        float ern = g_er[r * NN + n];
        const float* elr = g_el + r * NN;
        const int*   cs  = g_csr_src + (size_t)r * EE;
        const float* zr  = g_z + (size_t)r * NN * DD;

        // pass A: max of leaky logits (all lanes redundantly, broadcast loads)
        float vmax = -1e30f;
        for (int idx = b0; idx < b1; ++idx) {
            float v = elr[cs[idx]] + ern;
            v = v > 0.f ? v : 0.2f * v;
            vmax = fmaxf(vmax, v);
        }
        // pass B: exp, sum, weighted gather
        float4 acc = make_float4(0.f, 0.f, 0.f, 0.f);
        float ssum = 0.f;
        for (int idx = b0; idx < b1; ++idx) {
            int s = cs[idx];
            float v = elr[s] + ern;
            v = v > 0.f ? v : 0.2f * v;
            float a = __expf(v - vmax);
            ssum += a;
            float4 zv = *(const float4*)(zr + (size_t)s * DD + lane * 4);
            acc.x += a * zv.x; acc.y += a * zv.y;
            acc.z += a * zv.z; acc.w += a * zv.w;
        }
        float inv = (b1 > b0) ? (1.f / ssum) : 0.f;
        float4 bv = *(const float4*)(bias_layer + r * DD + lane * 4);
        float4 v4 = make_float4(acc.x * inv + hv.x + bv.x,
                                acc.y * inv + hv.y + bv.y,
                                acc.z * inv + hv.z + bv.z,
                                acc.w * inv + hv.w + bv.w);
        if (dorelu) {
            v4.x = fmaxf(v4.x, 0.f); v4.y = fmaxf(v4.y, 0.f);
            v4.z = fmaxf(v4.z, 0.f); v4.w = fmaxf(v4.w, 0.f);
        }
        tot.x += v4.x; tot.y += v4.y; tot.z += v4.z; tot.w += v4.w;
    }
    *(float4*)(t + (size_t)n * DD + lane * 4) = tot;
}

// ---------------- BatchNorm ----------------
__global__ void bnstat_kernel(const float* __restrict__ t) {
    int col  = threadIdx.x & 127;
    int half = threadIdx.x >> 7;
    float s = 0.f, s2 = 0.f;
    for (int n = blockIdx.x * 2 + half; n < NN; n += gridDim.x * 2) {
        float v = t[(size_t)n * DD + col];
        s += v; s2 += v * v;
    }
    __shared__ float sh[256], sh2[256];
    sh[threadIdx.x] = s; sh2[threadIdx.x] = s2;
    __syncthreads();
    if (half == 0) {
        s  += sh[threadIdx.x + 128];
        s2 += sh2[threadIdx.x + 128];
        atomicAdd(&g_sum[col], s);
        atomicAdd(&g_sumsq[col], s2);
    }
}

__global__ void bnfin_kernel(const float* __restrict__ gamma, const float* __restrict__ beta) {
    int c = threadIdx.x;
    float invN = 1.f / (float)NN;
    float mu  = g_sum[c] * invN;
    float var = g_sumsq[c] * invN - mu * mu;
    float rs  = rsqrtf(var + 1e-5f);
    float g   = gamma[c];
    g_scale[c] = rs * g;
    g_shift[c] = beta[c] - mu * rs * g;
    g_sum[c] = 0.f;      // reset for next layer / next replay
    g_sumsq[c] = 0.f;
}

__global__ void bnnorm_kernel(const float* __restrict__ t, float* __restrict__ outp) {
    size_t i = (size_t)blockIdx.x * blockDim.x + threadIdx.x;
    if (i >= (size_t)NN * DD / 4) return;
    int c4 = (int)(i & 31) * 4;
    float4 v = ((const float4*)t)[i];
    v.x = v.x * g_scale[c4 + 0] + g_shift[c4 + 0];
    v.y = v.y * g_scale[c4 + 1] + g_shift[c4 + 1];
    v.z = v.z * g_scale[c4 + 2] + g_shift[c4 + 2];
    v.w = v.w * g_scale[c4 + 3] + g_shift[c4 + 3];
    ((float4*)outp)[i] = v;
}

// ---------------- launcher ----------------
extern "C" void kernel_launch(void* const* d_in, const int* in_sizes, int n_in,
                              void* d_out, int out_size) {
    const float* x     = (const float*)d_in[0];
    const int*   src   = (const int*)d_in[1];
    const int*   dst   = (const int*)d_in[2];
    const float* Ws    = (const float*)d_in[3];
    const float* attnl = (const float*)d_in[4];
    const float* attnr = (const float*)d_in[5];
    const float* bias  = (const float*)d_in[6];
    const float* gamma = (const float*)d_in[7];
    const float* beta  = (const float*)d_in[8];
    float* out = (float*)d_out;

    float *p_b0 = nullptr, *p_b1 = nullptr;
    int* p_cnt = nullptr;
    cudaGetSymbolAddress((void**)&p_b0, g_b0);
    cudaGetSymbolAddress((void**)&p_b1, g_b1);
    cudaGetSymbolAddress((void**)&p_cnt, g_cnt);

    dim3 gemm_grid((NN + BM - 1) / BM, RR);
    dim3 edge_grid((EE + 255) / 256, RR);
    dim3 scan_grid(SCAN_B, RR);
    int heavy_blocks = (NN * 32 + 255) / 256;
    int norm_blocks  = ((NN * DD / 4) + 255) / 256;

    // ---- CSR build: once per launch (graph is layer-invariant) ----
    cudaMemsetAsync(p_cnt, 0, (size_t)RR * NN * sizeof(int));
    count_kernel<<<edge_grid, 256>>>(dst);
    scan1_kernel<<<scan_grid, 1024>>>();
    scan2_kernel<<<1, 32>>>();
    scan3_kernel<<<scan_grid, 1024>>>();
    fill_kernel<<<edge_grid, 256>>>(src, dst);

    for (int i = 0; i < LL; i++) {
        const float* hin = (i == 0) ? x : (i == 1 ? p_b0 : p_b1);
        float* tbuf      = (i == 0) ? p_b0 : (i == 1 ? p_b1 : out);

        gemm_attn_kernel<<<gemm_grid, 256>>>(hin,
                                             Ws    + (size_t)i * RR * DD * DD,
                                             attnl + (size_t)i * RR * DD,
                                             attnr + (size_t)i * RR * DD);
        heavy_all_kernel<<<heavy_blocks, 256>>>(hin,
                                                bias + (size_t)i * RR * DD,
                                                tbuf, /*dorelu=*/(i < LL - 1));
        bnstat_kernel<<<296, 256>>>(tbuf);
        bnfin_kernel<<<1, DD>>>(gamma + (size_t)i * DD, beta + (size_t)i * DD);
        bnnorm_kernel<<<norm_blocks, 256>>>(tbuf, tbuf);
    }
}